// round 13
// baseline (speedup 1.0000x reference)
#include <cuda_runtime.h>
#include <cuda_bf16.h>
#include <cstdint>

#define NB 2
#define NH 8
#define SEQ 4096
#define DK 128
#define DV 128
#define CHK 32
#define NCHUNK 128
#define BHN (NB*NH)
#define TOTAL_CHUNKS (BHN*NCHUNK)  // 2048
#define O_ELEMS (NB*NH*SEQ*DV)
#define S_ELEMS (NB*NH*DK*DV)

// ---- scratch ----
// g_wp[chunk][dd][i][2] = {-w(i,2dd), -w(i,2dd+1)}
// g_qp[chunk][dd][i][2] = { q(i,2dd),  q(i,2dd+1)}
// g_k [chunk][i][d]     plain k rows
// g_a [chunk][i][t]     plain att rows
// g_u [chunk][i][j]     u = T @ (v*beta)
__device__ float g_wp[(size_t)TOTAL_CHUNKS*4096];
__device__ float g_qp[(size_t)TOTAL_CHUNKS*4096];
__device__ float g_k [(size_t)TOTAL_CHUNKS*4096];
__device__ float g_a [(size_t)TOTAL_CHUNKS*1024];
__device__ float g_u [(size_t)TOTAL_CHUNKS*4096];
__device__ int   g_flag[TOTAL_CHUNKS];

typedef unsigned long long u64t;

__device__ __forceinline__ void ffma2(u64t& d, u64t a, u64t b) {
    asm("fma.rn.f32x2 %0, %1, %2, %0;" : "+l"(d) : "l"(a), "l"(b));
}
__device__ __forceinline__ u64t addf2(u64t a, u64t b) {
    u64t d; asm("add.rn.f32x2 %0, %1, %2;" : "=l"(d) : "l"(a), "l"(b)); return d;
}
__device__ __forceinline__ u64t dupf(float x) {
    u64t d; asm("mov.b64 %0, {%1, %1};" : "=l"(d) : "f"(x)); return d;
}
__device__ __forceinline__ float2 unpk(u64t v) {
    float2 f; asm("mov.b64 {%0, %1}, %2;" : "=f"(f.x), "=f"(f.y) : "l"(v)); return f;
}
__device__ __forceinline__ void cpa16(uint32_t s, const void* g) {
    asm volatile("cp.async.cg.shared.global [%0], [%1], 16;" :: "r"(s), "l"(g));
}
__device__ __forceinline__ void cpa_commit() { asm volatile("cp.async.commit_group;"); }
__device__ __forceinline__ void cpa_wait0()  { asm volatile("cp.async.wait_group 0;" ::: "memory"); }
__device__ __forceinline__ int ldacq(const int* p) {
    int v; asm volatile("ld.acquire.gpu.global.b32 %0, [%1];" : "=r"(v) : "l"(p)); return v;
}

// prep role smem layout (floats)
#define RS 132
#define TS 36
#define PF_QS 0
#define PF_KS 4224
#define PF_VS 8448
#define PF_KT 12672   // 128 x 36 = 4608
#define PF_A  17280
#define PF_B  18304
#define PF_R  18336
#define PF_AT 18400   // 1024; end 19424

// scan role smem layout (floats)
#define SM_S    0
#define SM_WP   2048
#define SM_QP   6144
#define SM_K    10240    // 2 x 4096
#define SM_AT   18432    // 2 x 1024
#define SM_CMB  20480
#define SM_UN   21504
#define SM_TOT  22016    // 88064 bytes

// ============================================================================
__device__ __forceinline__ void prep_role(
    float* sm, const float* __restrict__ q, const float* __restrict__ k,
    const float* __restrict__ v, const float* __restrict__ beta, int p)
{
    float* qs    = sm + PF_QS;
    float* ks    = sm + PF_KS;
    float* vs    = sm + PF_VS;
    float* kT    = sm + PF_KT;
    float* A     = sm + PF_A;
    float* betas = sm + PF_B;
    float* rinv  = sm + PF_R;
    float* attS  = sm + PF_AT;

    const int tid  = threadIdx.x;
    const int lane = tid & 31;
    const int wid  = tid >> 5;
    const int chunk = (p & 15) * NCHUNK + (p >> 4);   // t-major production order
    const size_t base = (size_t)chunk * (CHK*DK);

    // --- load tiles + beta ---
    for (int e = tid; e < 1024; e += 256) {
        int r = e >> 5, c4 = (e & 31) * 4;
        *(float4*)(qs + r*RS + c4) = *(const float4*)(q + base + r*DK + c4);
        *(float4*)(ks + r*RS + c4) = *(const float4*)(k + base + r*DK + c4);
        *(float4*)(vs + r*RS + c4) = *(const float4*)(v + base + r*DK + c4);
    }
    if (tid < CHK) betas[tid] = beta[(size_t)chunk*CHK + tid];
    __syncthreads();

    // --- row l2-norms via warp shuffle ---
    {
        const float* srcb = (wid < 4) ? qs : ks;
        int rbase = (wid & 3) * 8;
        #pragma unroll
        for (int rr = 0; rr < 8; rr++) {
            int r = rbase + rr;
            float4 x = *(const float4*)(srcb + r*RS + lane*4);
            float s = x.x*x.x + x.y*x.y + x.z*x.z + x.w*x.w;
            #pragma unroll
            for (int off = 16; off > 0; off >>= 1)
                s += __shfl_xor_sync(0xffffffffu, s, off);
            if (lane == 0) rinv[((wid < 4) ? 0 : 32) + r] = rsqrtf(s + 1e-6f);
        }
    }
    __syncthreads();

    // --- fused scale + kT build ---
    for (int e = tid; e < 4096; e += 256) {
        int r = e >> 7, c = e & 127;
        float qv = qs[r*RS + c] * rinv[r];
        float kv = ks[r*RS + c] * rinv[32 + r];
        qs[r*RS + c] = qv;
        ks[r*RS + c] = kv;  kT[c*TS + r] = kv;
        vs[r*RS + c] *= betas[r];
    }
    __syncthreads();

    const int ti = (tid >> 4) * 2;
    const int tj = (tid & 15) * 2;

    // --- A (pre-inversion) and att 2x2 tiles, d batched by 2 (float2 operands) ---
    {
        u64t kA0 = 0ull, kA1 = 0ull, aA0 = 0ull, aA1 = 0ull;
        #pragma unroll 8
        for (int d = 0; d < DK; d += 2) {
            u64t kb0 = *(const u64t*)(kT + d*TS + tj);
            u64t kb1 = *(const u64t*)(kT + (d+1)*TS + tj);
            float2 ka0 = *(const float2*)(ks + ti*RS + d);
            float2 ka1 = *(const float2*)(ks + (ti+1)*RS + d);
            float2 qa0 = *(const float2*)(qs + ti*RS + d);
            float2 qa1 = *(const float2*)(qs + (ti+1)*RS + d);
            ffma2(kA0, dupf(ka0.x), kb0); ffma2(kA0, dupf(ka0.y), kb1);
            ffma2(kA1, dupf(ka1.x), kb0); ffma2(kA1, dupf(ka1.y), kb1);
            ffma2(aA0, dupf(qa0.x), kb0); ffma2(aA0, dupf(qa0.y), kb1);
            ffma2(aA1, dupf(qa1.x), kb0); ffma2(aA1, dupf(qa1.y), kb1);
        }
        float2 k0 = unpk(kA0), k1 = unpk(kA1), a0 = unpk(aA0), a1 = unpk(aA1);
        float bi0 = betas[ti], bi1 = betas[ti+1];
        A[(ti  )*32 + tj  ] = (tj   < ti  ) ? -bi0*k0.x : 0.f;
        A[(ti  )*32 + tj+1] = (tj+1 < ti  ) ? -bi0*k0.y : 0.f;
        A[(ti+1)*32 + tj  ] = (tj   < ti+1) ? -bi1*k1.x : 0.f;
        A[(ti+1)*32 + tj+1] = (tj+1 < ti+1) ? -bi1*k1.y : 0.f;
        attS[(ti  )*32 + tj  ] = (tj   <= ti  ) ? a0.x : 0.f;
        attS[(ti  )*32 + tj+1] = (tj+1 <= ti  ) ? a0.y : 0.f;
        attS[(ti+1)*32 + tj  ] = (tj   <= ti+1) ? a1.x : 0.f;
        attS[(ti+1)*32 + tj+1] = (tj+1 <= ti+1) ? a1.y : 0.f;
    }
    __syncthreads();

    // --- OVERLAP: warp 0 inverts (I-A) + adds I + bf16-rounds,
    //     warps 1-7 write qp/k/att to global ---
    if (wid == 0) {
        for (int i = 1; i < CHK; i++) {
            float upd = 0.f;
            if (lane < i) {
                for (int j = 0; j < i; j++) upd += A[i*CHK + j] * A[j*CHK + lane];
            }
            __syncwarp();
            if (lane < i) A[i*CHK + lane] += upd;
            __syncwarp();
        }
        for (int o = lane; o < 1024; o += 32) {
            int i = o >> 5, j = o & 31;
            float val = A[o] + ((i == j) ? 1.f : 0.f);
            A[o] = __bfloat162float(__float2bfloat16(val));
        }
    } else {
        const int t0 = tid - 32;   // 0..223
        for (int idx = t0; idx < 2048; idx += 224) {
            int ii = idx >> 6, dd = idx & 63;
            float2 ab = *(const float2*)(qs + ii*RS + 2*dd);
            *(float2*)(g_qp + (size_t)chunk*4096 + (dd*32 + ii)*2) = ab;
        }
        for (int idx = t0; idx < 1024; idx += 224) {
            int r = idx >> 5, c4 = (idx & 31) * 4;
            *(float4*)(g_k + (size_t)chunk*4096 + r*128 + c4) =
                *(const float4*)(ks + r*RS + c4);
        }
        for (int idx = t0; idx < 256; idx += 224) {
            *(float4*)(g_a + (size_t)chunk*1024 + idx*4) = *(const float4*)(attS + idx*4);
        }
    }
    __syncthreads();

    // --- u = T@(v*beta) -> g_u ; w = T@(beta*k) -> g_wp (pairs, negated) ---
    //     operands via LDS.128 (ulonglong2)
    {
        int i  = tid >> 3;
        int cb = (tid & 7) * 16;
        u64t ua[8], wa[8];
        #pragma unroll
        for (int m = 0; m < 8; m++) { ua[m] = 0ull; wa[m] = 0ull; }
        for (int t = 0; t < CHK; t++) {
            float a  = A[i*CHK + t];
            u64t  au = dupf(a);
            u64t  ab = dupf(a * betas[t]);
            const ulonglong2* vr = (const ulonglong2*)(vs + t*RS + cb);
            const ulonglong2* kr = (const ulonglong2*)(ks + t*RS + cb);
            #pragma unroll
            for (int m = 0; m < 4; m++) {
                ulonglong2 vv = vr[m];
                ulonglong2 kk = kr[m];
                ffma2(ua[2*m],   au, vv.x); ffma2(ua[2*m+1], au, vv.y);
                ffma2(wa[2*m],   ab, kk.x); ffma2(wa[2*m+1], ab, kk.y);
            }
        }
        float* up = g_u + (size_t)chunk*4096 + i*DV + cb;
        #pragma unroll
        for (int m = 0; m < 8; m += 2) {
            ulonglong2 w2; w2.x = ua[m]; w2.y = ua[m+1];
            *(ulonglong2*)(up + 2*m) = w2;
        }
        #pragma unroll
        for (int m = 0; m < 8; m++) {
            float2 w2 = unpk(wa[m]);
            int dd = (cb >> 1) + m;
            *(float2*)(g_wp + (size_t)chunk*4096 + (dd*32 + i)*2) =
                make_float2(-w2.x, -w2.y);
        }
    }

    // --- publish ---
    __threadfence();
    __syncthreads();
    if (tid == 0) atomicExch(&g_flag[chunk], 1);
}

// ============================================================================
__device__ __forceinline__ void stage_chunk(float* sm, size_t ch, int nbuf, int tid)
{
    uint32_t swp = (uint32_t)__cvta_generic_to_shared(sm + SM_WP);
    uint32_t sqp = (uint32_t)__cvta_generic_to_shared(sm + SM_QP);
    uint32_t sk  = (uint32_t)__cvta_generic_to_shared(sm + SM_K  + nbuf*4096);
    uint32_t sa  = (uint32_t)__cvta_generic_to_shared(sm + SM_AT + nbuf*1024);
    const float4* gw = (const float4*)(g_wp + ch*4096);
    const float4* gq = (const float4*)(g_qp + ch*4096);
    const float4* gk = (const float4*)(g_k  + ch*4096);
    const float4* ga = (const float4*)(g_a  + ch*1024);
    for (int e = tid; e < 1024; e += 256) {
        cpa16(swp + e*16, gw + e);
        cpa16(sqp + e*16, gq + e);
        cpa16(sk  + e*16, gk + e);
    }
    for (int e = tid; e < 256; e += 256) cpa16(sa + e*16, ga + e);
    cpa_commit();
}

__device__ __forceinline__ void scan_role(float* sm, float* __restrict__ out, int write_state)
{
    float* S  = sm + SM_S;
    float* WP = sm + SM_WP;
    float* QP = sm + SM_QP;
    float* K  = sm + SM_K;
    float* AT = sm + SM_AT;
    float* CMB= sm + SM_CMB;
    float* UN = sm + SM_UN;

    const int tid = threadIdx.x;
    const int bh = blockIdx.x >> 3;
    const int j0 = (blockIdx.x & 7) * 16;

    const int kh = tid >> 7;
    const int r  = (tid >> 2) & 31;
    const int cq = (tid & 3) * 4;
    const int lid128 = tid & 127;
    const int dp = tid >> 2;
    const int c2 = (tid & 3) * 4;

    for (int e = tid; e < 2048; e += 256) S[e] = 0.f;

    const size_t cbase = (size_t)bh * NCHUNK;

    while (ldacq(&g_flag[cbase]) == 0) {}
    ulonglong2 uc;
    if (kh == 0) uc = *(const ulonglong2*)(g_u + cbase*4096 + r*DV + j0 + cq);
    stage_chunk(sm, cbase, 0, tid);
    cpa_wait0();
    __syncthreads();
    if (tid == 0) { int old = atomicAdd(&g_flag[cbase], 1); if (old == 8) g_flag[cbase] = 0; }

    for (int t = 0; t < NCHUNK; t++) {
        const int buf = t & 1;
        const int nbuf = buf ^ 1;
        const float* Kb  = K  + buf*4096;
        const float* ATb = AT + buf*1024;

        // ---- Pass 1 (split-K): u_new = u - w@S ; o_part = q@S ----
        u64t u0, u1, o0 = 0ull, o1 = 0ull;
        if (kh == 0) { u0 = uc.x; u1 = uc.y; } else { u0 = 0ull; u1 = 0ull; }
        {
            const int d0 = kh * 32;
            #pragma unroll 8
            for (int m = 0; m < 32; m++) {
                int dd = d0 + m;
                float2 wf = *(const float2*)(WP + (dd*32 + r)*2);
                float2 qf = *(const float2*)(QP + (dd*32 + r)*2);
                const ulonglong2 s0 = *(const ulonglong2*)(S + (2*dd  )*16 + cq);
                const ulonglong2 s1 = *(const ulonglong2*)(S + (2*dd+1)*16 + cq);
                u64t wx = dupf(wf.x), wy = dupf(wf.y);
                u64t qx = dupf(qf.x), qy = dupf(qf.y);
                ffma2(u0, wx, s0.x); ffma2(u1, wx, s0.y);
                ffma2(u0, wy, s1.x); ffma2(u1, wy, s1.y);
                ffma2(o0, qx, s0.x); ffma2(o1, qx, s0.y);
                ffma2(o0, qy, s1.x); ffma2(o1, qy, s1.y);
            }
        }
        __syncthreads();   // bar1

        // ---- prefetch chunk t+1 (+ u carry) ----
        const int has_next = (t+1 < NCHUNK);
        const size_t ch = cbase + (has_next ? t+1 : t);
        if (has_next) { while (ldacq(&g_flag[ch]) == 0) {} }
        if (kh == 0) uc = *(const ulonglong2*)(g_u + ch*4096 + r*DV + j0 + cq);
        stage_chunk(sm, ch, nbuf, tid);

        // ---- combine #1: kh=1 partials -> kh=0 ; write UN ----
        if (kh) {
            ulonglong2 w2;
            w2.x = u0; w2.y = u1; *(ulonglong2*)(CMB + lid128*8    ) = w2;
            w2.x = o0; w2.y = o1; *(ulonglong2*)(CMB + lid128*8 + 4) = w2;
            o0 = 0ull; o1 = 0ull;
        }
        __syncthreads();   // bar2
        if (!kh) {
            ulonglong2 pu = *(const ulonglong2*)(CMB + lid128*8);
            ulonglong2 po = *(const ulonglong2*)(CMB + lid128*8 + 4);
            u0 = addf2(u0, pu.x); u1 = addf2(u1, pu.y);
            o0 = addf2(o0, po.x); o1 = addf2(o1, po.y);
            ulonglong2 w2; w2.x = u0; w2.y = u1;
            *(ulonglong2*)(UN + r*16 + cq) = w2;
        }
        __syncthreads();   // bar3: UN ready

        // ---- Pass 2a (split-T): o += att_local @ u_new ----
        {
            const int t0 = kh * 8;
            #pragma unroll 4
            for (int m = 0; m < 8; m++) {
                int tt = t0 + m;
                float2 av = *(const float2*)(ATb + r*32 + 2*tt);
                u64t ax = dupf(av.x), ay = dupf(av.y);
                const ulonglong2 n0 = *(const ulonglong2*)(UN + (2*tt  )*16 + cq);
                const ulonglong2 n1 = *(const ulonglong2*)(UN + (2*tt+1)*16 + cq);
                ffma2(o0, ax, n0.x); ffma2(o1, ax, n0.y);
                ffma2(o0, ay, n1.x); ffma2(o1, ay, n1.y);
            }
        }
        if (kh) {
            ulonglong2 w2; w2.x = o0; w2.y = o1;
            *(ulonglong2*)(CMB + lid128*4) = w2;
        }
        __syncthreads();   // bar4
        if (!kh) {
            ulonglong2 po = *(const ulonglong2*)(CMB + lid128*4);
            o0 = addf2(o0, po.x); o1 = addf2(o1, po.y);
            ulonglong2 w2; w2.x = o0; w2.y = o1;
            *(ulonglong2*)(out + ((size_t)bh*SEQ + (size_t)t*CHK + r)*DV + j0 + cq) = w2;
        }

        // ---- Pass 2b: S += k^T @ u_new ----
        {
            ulonglong2 r0 = *(const ulonglong2*)(S + (2*dp  )*16 + c2);
            ulonglong2 r1 = *(const ulonglong2*)(S + (2*dp+1)*16 + c2);
            #pragma unroll 8
            for (int i = 0; i < CHK; i++) {
                float2 kp = *(const float2*)(Kb + i*128 + 2*dp);
                u64t kx = dupf(kp.x), ky = dupf(kp.y);
                const ulonglong2 na = *(const ulonglong2*)(UN + i*16 + c2);
                ffma2(r0.x, kx, na.x); ffma2(r0.y, kx, na.y);
                ffma2(r1.x, ky, na.x); ffma2(r1.y, ky, na.y);
            }
            *(ulonglong2*)(S + (2*dp  )*16 + c2) = r0;
            *(ulonglong2*)(S + (2*dp+1)*16 + c2) = r1;
        }

        cpa_wait0();
        __syncthreads();   // bar5
        if (has_next && tid == 0) {
            int old = atomicAdd(&g_flag[ch], 1);
            if (old == 8) g_flag[ch] = 0;
        }
    }

    if (write_state) {
        const int d = tid >> 1;
        const int c = (tid & 1) * 8;
        *(float4*)(out + (size_t)O_ELEMS + (size_t)bh*(DK*DV) + d*DV + j0 + c) =
            *(const float4*)(S + d*16 + c);
        *(float4*)(out + (size_t)O_ELEMS + (size_t)bh*(DK*DV) + d*DV + j0 + c + 4) =
            *(const float4*)(S + d*16 + c + 4);
    }
}

// ============================================================================
__global__ __launch_bounds__(256, 2) void fused_kernel(
    const float* __restrict__ q, const float* __restrict__ k,
    const float* __restrict__ v, const float* __restrict__ beta,
    float* __restrict__ out, int write_state)
{
    extern __shared__ float sm[];
    if (blockIdx.x < BHN*8) {
        scan_role(sm, out, write_state);
    } else {
        prep_role(sm, q, k, v, beta, blockIdx.x - BHN*8);
    }
}

// ============================================================================
extern "C" void kernel_launch(void* const* d_in, const int* in_sizes, int n_in,
                              void* d_out, int out_size) {
    const float* q    = (const float*)d_in[0];
    const float* k    = (const float*)d_in[1];
    const float* v    = (const float*)d_in[2];
    const float* beta = (const float*)d_in[3];
    float* out = (float*)d_out;

    const int smem = SM_TOT * 4;   // 88064 B
    cudaFuncSetAttribute(fused_kernel, cudaFuncAttributeMaxDynamicSharedMemorySize, smem);

    const int write_state = (out_size >= O_ELEMS + S_ELEMS) ? 1 : 0;

    fused_kernel<<<BHN*8 + TOTAL_CHUNKS, 256, smem>>>(q, k, v, beta, out, write_state);
}

// round 14
// speedup vs baseline: 1.6324x; 1.6324x over previous
#include <cuda_runtime.h>
#include <cuda_bf16.h>
#include <cstdint>

#define NB 2
#define NH 8
#define SEQ 4096
#define DK 128
#define DV 128
#define CHK 32
#define NCHUNK 128
#define BHN (NB*NH)
#define TOTAL_CHUNKS (BHN*NCHUNK)  // 2048
#define O_ELEMS (NB*NH*SEQ*DV)
#define S_ELEMS (NB*NH*DK*DV)

// ---- scratch ----
// g_wp[chunk][dd][i][2] = {-w(i,2dd), -w(i,2dd+1)}
// g_qp[chunk][dd][i][2] = { q(i,2dd),  q(i,2dd+1)}
// g_k [chunk][i][d]     plain k rows
// g_a [chunk][i][t]     plain att rows
// g_u [chunk][i][j]     u = T @ (v*beta)
__device__ float g_wp[(size_t)TOTAL_CHUNKS*4096];
__device__ float g_qp[(size_t)TOTAL_CHUNKS*4096];
__device__ float g_k [(size_t)TOTAL_CHUNKS*4096];
__device__ float g_a [(size_t)TOTAL_CHUNKS*1024];
__device__ float g_u [(size_t)TOTAL_CHUNKS*4096];
__device__ int   g_flag[TOTAL_CHUNKS];   // 0 idle; 1 ready; 1+n after n consumers; reset by 8th

typedef unsigned long long u64t;

__device__ __forceinline__ void ffma2(u64t& d, u64t a, u64t b) {
    asm("fma.rn.f32x2 %0, %1, %2, %0;" : "+l"(d) : "l"(a), "l"(b));
}
__device__ __forceinline__ u64t addf2(u64t a, u64t b) {
    u64t d; asm("add.rn.f32x2 %0, %1, %2;" : "=l"(d) : "l"(a), "l"(b)); return d;
}
__device__ __forceinline__ u64t dupf(float x) {
    u64t d; asm("mov.b64 %0, {%1, %1};" : "=l"(d) : "f"(x)); return d;
}
__device__ __forceinline__ float2 unpk(u64t v) {
    float2 f; asm("mov.b64 {%0, %1}, %2;" : "=f"(f.x), "=f"(f.y) : "l"(v)); return f;
}
__device__ __forceinline__ void cpa16(uint32_t s, const void* g) {
    asm volatile("cp.async.cg.shared.global [%0], [%1], 16;" :: "r"(s), "l"(g));
}
__device__ __forceinline__ void cpa_commit() { asm volatile("cp.async.commit_group;"); }
__device__ __forceinline__ void cpa_wait0()  { asm volatile("cp.async.wait_group 0;" ::: "memory"); }
__device__ __forceinline__ int ldacq(const int* p) {
    int v; asm volatile("ld.acquire.gpu.global.b32 %0, [%1];" : "=r"(v) : "l"(p)); return v;
}

// prep role smem layout (floats)
#define RS 132
#define TS 36
#define PF_QS 0
#define PF_KS 4224
#define PF_VS 8448
#define PF_KT 12672   // 128 x 36 = 4608
#define PF_A  17280
#define PF_B  18304
#define PF_R  18336
#define PF_AT 18400   // 1024; end 19424

// scan role smem layout (floats)
#define SM_S    0        // 2048
#define SM_WP   2048     // 4096
#define SM_QP   6144     // 4096
#define SM_K    10240    // 2 x 4096
#define SM_AT   18432    // 2 x 1024
#define SM_CMB  20480    // 1024
#define SM_UN   21504    // 512
#define SM_TOT  22016    // 88064 bytes

// ============================================================================
__device__ __forceinline__ void prep_role(
    float* sm, const float* __restrict__ q, const float* __restrict__ k,
    const float* __restrict__ v, const float* __restrict__ beta, int p)
{
    float* qs    = sm + PF_QS;
    float* ks    = sm + PF_KS;
    float* vs    = sm + PF_VS;
    float* kT    = sm + PF_KT;
    float* A     = sm + PF_A;
    float* betas = sm + PF_B;
    float* rinv  = sm + PF_R;
    float* attS  = sm + PF_AT;

    const int tid  = threadIdx.x;
    const int lane = tid & 31;
    const int wid  = tid >> 5;
    const int chunk = (p & 15) * NCHUNK + (p >> 4);   // t-major production order
    const size_t base = (size_t)chunk * (CHK*DK);

    // --- load tiles + beta ---
    for (int e = tid; e < 1024; e += 256) {
        int r = e >> 5, c4 = (e & 31) * 4;
        *(float4*)(qs + r*RS + c4) = *(const float4*)(q + base + r*DK + c4);
        *(float4*)(ks + r*RS + c4) = *(const float4*)(k + base + r*DK + c4);
        *(float4*)(vs + r*RS + c4) = *(const float4*)(v + base + r*DK + c4);
    }
    if (tid < CHK) betas[tid] = beta[(size_t)chunk*CHK + tid];
    __syncthreads();

    // --- row l2-norms via warp shuffle ---
    {
        const float* srcb = (wid < 4) ? qs : ks;
        int rbase = (wid & 3) * 8;
        #pragma unroll
        for (int rr = 0; rr < 8; rr++) {
            int r = rbase + rr;
            float4 x = *(const float4*)(srcb + r*RS + lane*4);
            float s = x.x*x.x + x.y*x.y + x.z*x.z + x.w*x.w;
            #pragma unroll
            for (int off = 16; off > 0; off >>= 1)
                s += __shfl_xor_sync(0xffffffffu, s, off);
            if (lane == 0) rinv[((wid < 4) ? 0 : 32) + r] = rsqrtf(s + 1e-6f);
        }
    }
    __syncthreads();

    // --- fused scale + kT build ---
    for (int e = tid; e < 4096; e += 256) {
        int r = e >> 7, c = e & 127;
        float qv = qs[r*RS + c] * rinv[r];
        float kv = ks[r*RS + c] * rinv[32 + r];
        qs[r*RS + c] = qv;
        ks[r*RS + c] = kv;  kT[c*TS + r] = kv;
        vs[r*RS + c] *= betas[r];
    }
    __syncthreads();

    // --- A (pre-inversion) and att 2x2 tiles ---
    {
        const int ti = (tid >> 4) * 2;
        const int tj = (tid & 15) * 2;
        u64t kA0 = 0ull, kA1 = 0ull, aA0 = 0ull, aA1 = 0ull;
        #pragma unroll 8
        for (int d = 0; d < DK; d++) {
            u64t kb = *(const u64t*)(kT + d*TS + tj);
            float ka0 = ks[ti*RS + d],     ka1 = ks[(ti+1)*RS + d];
            float qa0 = qs[ti*RS + d],     qa1 = qs[(ti+1)*RS + d];
            ffma2(kA0, dupf(ka0), kb);
            ffma2(kA1, dupf(ka1), kb);
            ffma2(aA0, dupf(qa0), kb);
            ffma2(aA1, dupf(qa1), kb);
        }
        float2 k0 = unpk(kA0), k1 = unpk(kA1), a0 = unpk(aA0), a1 = unpk(aA1);
        float bi0 = betas[ti], bi1 = betas[ti+1];
        A[(ti  )*32 + tj  ] = (tj   < ti  ) ? -bi0*k0.x : 0.f;
        A[(ti  )*32 + tj+1] = (tj+1 < ti  ) ? -bi0*k0.y : 0.f;
        A[(ti+1)*32 + tj  ] = (tj   < ti+1) ? -bi1*k1.x : 0.f;
        A[(ti+1)*32 + tj+1] = (tj+1 < ti+1) ? -bi1*k1.y : 0.f;
        attS[(ti  )*32 + tj  ] = (tj   <= ti  ) ? a0.x : 0.f;
        attS[(ti  )*32 + tj+1] = (tj+1 <= ti  ) ? a0.y : 0.f;
        attS[(ti+1)*32 + tj  ] = (tj   <= ti+1) ? a1.x : 0.f;
        attS[(ti+1)*32 + tj+1] = (tj+1 <= ti+1) ? a1.y : 0.f;
    }
    __syncthreads();

    // --- OVERLAP: warp 0 inverts + bf16-rounds A; warps 1-7 write qp/k/att ---
    if (wid == 0) {
        for (int i = 1; i < CHK; i++) {
            float upd = 0.f;
            if (lane < i) {
                for (int j = 0; j < i; j++) upd += A[i*CHK + j] * A[j*CHK + lane];
            }
            __syncwarp();
            if (lane < i) A[i*CHK + lane] += upd;
            __syncwarp();
        }
        for (int o = lane; o < 1024; o += 32) {
            int i = o >> 5, j = o & 31;
            float val = A[o] + ((i == j) ? 1.f : 0.f);
            A[o] = __bfloat162float(__float2bfloat16(val));
        }
    } else {
        const int t0 = tid - 32;   // 0..223
        for (int idx = t0; idx < 2048; idx += 224) {
            int ii = idx >> 6, dd = idx & 63;
            float2 ab = *(const float2*)(qs + ii*RS + 2*dd);
            *(float2*)(g_qp + (size_t)chunk*4096 + (dd*32 + ii)*2) = ab;
        }
        for (int idx = t0; idx < 1024; idx += 224) {
            int r = idx >> 5, c4 = (idx & 31) * 4;
            *(float4*)(g_k + (size_t)chunk*4096 + r*128 + c4) =
                *(const float4*)(ks + r*RS + c4);
        }
        for (int idx = t0; idx < 256; idx += 224) {
            *(float4*)(g_a + (size_t)chunk*1024 + idx*4) = *(const float4*)(attS + idx*4);
        }
    }
    __syncthreads();

    // --- u = T@(v*beta) -> g_u ; w = T@(beta*k) -> g_wp (pairs, negated) ---
    {
        int i  = tid >> 3;
        int cb = (tid & 7) * 16;
        u64t ua[8], wa[8];
        #pragma unroll
        for (int m = 0; m < 8; m++) { ua[m] = 0ull; wa[m] = 0ull; }
        for (int t = 0; t < CHK; t++) {
            float a  = A[i*CHK + t];
            u64t  au = dupf(a);
            u64t  ab = dupf(a * betas[t]);
            const u64t* vr = (const u64t*)(vs + t*RS + cb);
            const u64t* kr = (const u64t*)(ks + t*RS + cb);
            #pragma unroll
            for (int m = 0; m < 8; m++) { ffma2(ua[m], au, vr[m]); ffma2(wa[m], ab, kr[m]); }
        }
        float* up = g_u + (size_t)chunk*4096 + i*DV + cb;
        #pragma unroll
        for (int m = 0; m < 8; m += 2) {
            ulonglong2 w2; w2.x = ua[m]; w2.y = ua[m+1];
            *(ulonglong2*)(up + 2*m) = w2;
        }
        #pragma unroll
        for (int m = 0; m < 8; m++) {
            float2 w2 = unpk(wa[m]);
            int dd = (cb >> 1) + m;
            *(float2*)(g_wp + (size_t)chunk*4096 + (dd*32 + i)*2) =
                make_float2(-w2.x, -w2.y);
        }
    }

    // --- publish ---
    __threadfence();
    __syncthreads();
    if (tid == 0) atomicExch(&g_flag[chunk], 1);
}

// ============================================================================
__device__ __forceinline__ void stage_chunk(float* sm, size_t ch, int nbuf, int tid)
{
    uint32_t swp = (uint32_t)__cvta_generic_to_shared(sm + SM_WP);
    uint32_t sqp = (uint32_t)__cvta_generic_to_shared(sm + SM_QP);
    uint32_t sk  = (uint32_t)__cvta_generic_to_shared(sm + SM_K  + nbuf*4096);
    uint32_t sa  = (uint32_t)__cvta_generic_to_shared(sm + SM_AT + nbuf*1024);
    const float4* gw = (const float4*)(g_wp + ch*4096);
    const float4* gq = (const float4*)(g_qp + ch*4096);
    const float4* gk = (const float4*)(g_k  + ch*4096);
    const float4* ga = (const float4*)(g_a  + ch*1024);
    for (int e = tid; e < 1024; e += 256) {
        cpa16(swp + e*16, gw + e);
        cpa16(sqp + e*16, gq + e);
        cpa16(sk  + e*16, gk + e);
    }
    for (int e = tid; e < 256; e += 256) cpa16(sa + e*16, ga + e);
    cpa_commit();
}

__device__ __forceinline__ void scan_role(float* sm, float* __restrict__ out, int write_state)
{
    float* S  = sm + SM_S;
    float* WP = sm + SM_WP;
    float* QP = sm + SM_QP;
    float* K  = sm + SM_K;
    float* AT = sm + SM_AT;
    float* CMB= sm + SM_CMB;
    float* UN = sm + SM_UN;

    const int tid = threadIdx.x;
    const int bh = blockIdx.x >> 3;
    const int j0 = (blockIdx.x & 7) * 16;

    const int kh = tid >> 7;
    const int r  = (tid >> 2) & 31;
    const int cq = (tid & 3) * 4;
    const int lid128 = tid & 127;
    const int dp = tid >> 2;
    const int c2 = (tid & 3) * 4;

    for (int e = tid; e < 2048; e += 256) S[e] = 0.f;

    const size_t cbase = (size_t)bh * NCHUNK;

    while (ldacq(&g_flag[cbase]) == 0) {}
    ulonglong2 uc;
    if (kh == 0) uc = *(const ulonglong2*)(g_u + cbase*4096 + r*DV + j0 + cq);
    stage_chunk(sm, cbase, 0, tid);
    cpa_wait0();
    __syncthreads();
    if (tid == 0) { int old = atomicAdd(&g_flag[cbase], 1); if (old == 8) g_flag[cbase] = 0; }

    for (int t = 0; t < NCHUNK; t++) {
        const int buf = t & 1;
        const int nbuf = buf ^ 1;
        const float* Kb  = K  + buf*4096;
        const float* ATb = AT + buf*1024;

        // ---- Pass 1 (split-K): u_new = u - w@S ; o_part = q@S ----
        u64t u0, u1, o0 = 0ull, o1 = 0ull;
        if (kh == 0) { u0 = uc.x; u1 = uc.y; } else { u0 = 0ull; u1 = 0ull; }
        {
            const int d0 = kh * 32;
            #pragma unroll 8
            for (int m = 0; m < 32; m++) {
                int dd = d0 + m;
                float2 wf = *(const float2*)(WP + (dd*32 + r)*2);
                float2 qf = *(const float2*)(QP + (dd*32 + r)*2);
                const ulonglong2 s0 = *(const ulonglong2*)(S + (2*dd  )*16 + cq);
                const ulonglong2 s1 = *(const ulonglong2*)(S + (2*dd+1)*16 + cq);
                u64t wx = dupf(wf.x), wy = dupf(wf.y);
                u64t qx = dupf(qf.x), qy = dupf(qf.y);
                ffma2(u0, wx, s0.x); ffma2(u1, wx, s0.y);
                ffma2(u0, wy, s1.x); ffma2(u1, wy, s1.y);
                ffma2(o0, qx, s0.x); ffma2(o1, qx, s0.y);
                ffma2(o0, qy, s1.x); ffma2(o1, qy, s1.y);
            }
        }
        __syncthreads();   // bar1

        // ---- prefetch chunk t+1 (+ u carry) ----
        const int has_next = (t+1 < NCHUNK);
        const size_t ch = cbase + (has_next ? t+1 : t);
        if (has_next) { while (ldacq(&g_flag[ch]) == 0) {} }
        if (kh == 0) uc = *(const ulonglong2*)(g_u + ch*4096 + r*DV + j0 + cq);
        stage_chunk(sm, ch, nbuf, tid);

        // ---- combine #1: kh=1 partials -> kh=0 ; write UN ----
        if (kh) {
            ulonglong2 w2;
            w2.x = u0; w2.y = u1; *(ulonglong2*)(CMB + lid128*8    ) = w2;
            w2.x = o0; w2.y = o1; *(ulonglong2*)(CMB + lid128*8 + 4) = w2;
            o0 = 0ull; o1 = 0ull;
        }
        __syncthreads();   // bar2
        if (!kh) {
            ulonglong2 pu = *(const ulonglong2*)(CMB + lid128*8);
            ulonglong2 po = *(const ulonglong2*)(CMB + lid128*8 + 4);
            u0 = addf2(u0, pu.x); u1 = addf2(u1, pu.y);
            o0 = addf2(o0, po.x); o1 = addf2(o1, po.y);
            ulonglong2 w2; w2.x = u0; w2.y = u1;
            *(ulonglong2*)(UN + r*16 + cq) = w2;
        }
        __syncthreads();   // bar3: UN ready

        // ---- Pass 2a (split-T): o += att_local @ u_new ----
        {
            const int t0 = kh * 8;
            #pragma unroll 4
            for (int m = 0; m < 8; m++) {
                int tt = t0 + m;
                float2 av = *(const float2*)(ATb + r*32 + 2*tt);
                u64t ax = dupf(av.x), ay = dupf(av.y);
                const ulonglong2 n0 = *(const ulonglong2*)(UN + (2*tt  )*16 + cq);
                const ulonglong2 n1 = *(const ulonglong2*)(UN + (2*tt+1)*16 + cq);
                ffma2(o0, ax, n0.x); ffma2(o1, ax, n0.y);
                ffma2(o0, ay, n1.x); ffma2(o1, ay, n1.y);
            }
        }
        if (kh) {
            ulonglong2 w2; w2.x = o0; w2.y = o1;
            *(ulonglong2*)(CMB + lid128*4) = w2;
        }
        __syncthreads();   // bar4
        if (!kh) {
            ulonglong2 po = *(const ulonglong2*)(CMB + lid128*4);
            o0 = addf2(o0, po.x); o1 = addf2(o1, po.y);
            ulonglong2 w2; w2.x = o0; w2.y = o1;
            *(ulonglong2*)(out + ((size_t)bh*SEQ + (size_t)t*CHK + r)*DV + j0 + cq) = w2;
        }

        // ---- Pass 2b: S += k^T @ u_new ----
        {
            ulonglong2 r0 = *(const ulonglong2*)(S + (2*dp  )*16 + c2);
            ulonglong2 r1 = *(const ulonglong2*)(S + (2*dp+1)*16 + c2);
            #pragma unroll 8
            for (int i = 0; i < CHK; i++) {
                float2 kp = *(const float2*)(Kb + i*128 + 2*dp);
                u64t kx = dupf(kp.x), ky = dupf(kp.y);
                const ulonglong2 na = *(const ulonglong2*)(UN + i*16 + c2);
                ffma2(r0.x, kx, na.x); ffma2(r0.y, kx, na.y);
                ffma2(r1.x, ky, na.x); ffma2(r1.y, ky, na.y);
            }
            *(ulonglong2*)(S + (2*dp  )*16 + c2) = r0;
            *(ulonglong2*)(S + (2*dp+1)*16 + c2) = r1;
        }

        cpa_wait0();
        __syncthreads();   // bar5
        if (has_next && tid == 0) {
            int old = atomicAdd(&g_flag[ch], 1);
            if (old == 8) g_flag[ch] = 0;
        }
    }

    if (write_state) {
        const int d = tid >> 1;
        const int c = (tid & 1) * 8;
        *(float4*)(out + (size_t)O_ELEMS + (size_t)bh*(DK*DV) + d*DV + j0 + c) =
            *(const float4*)(S + d*16 + c);
        *(float4*)(out + (size_t)O_ELEMS + (size_t)bh*(DK*DV) + d*DV + j0 + c + 4) =
            *(const float4*)(S + d*16 + c + 4);
    }
}

// ============================================================================
__global__ __launch_bounds__(256, 2) void fused_kernel(
    const float* __restrict__ q, const float* __restrict__ k,
    const float* __restrict__ v, const float* __restrict__ beta,
    float* __restrict__ out, int write_state)
{
    extern __shared__ float sm[];
    if (blockIdx.x < BHN*8) {
        scan_role(sm, out, write_state);
    } else {
        prep_role(sm, q, k, v, beta, blockIdx.x - BHN*8);
    }
}

// ============================================================================
extern "C" void kernel_launch(void* const* d_in, const int* in_sizes, int n_in,
                              void* d_out, int out_size) {
    const float* q    = (const float*)d_in[0];
    const float* k    = (const float*)d_in[1];
    const float* v    = (const float*)d_in[2];
    const float* beta = (const float*)d_in[3];
    float* out = (float*)d_out;

    const int smem = SM_TOT * 4;   // 88064 B
    cudaFuncSetAttribute(fused_kernel, cudaFuncAttributeMaxDynamicSharedMemorySize, smem);

    const int write_state = (out_size >= O_ELEMS + S_ELEMS) ? 1 : 0;

    fused_kernel<<<BHN*8 + TOTAL_CHUNKS, 256, smem>>>(q, k, v, beta, out, write_state);
}